// round 1
// baseline (speedup 1.0000x reference)
#include <cuda_runtime.h>
#include <cuda_bf16.h>
#include <cstdint>

#define N_NODES 50000
#define N_EDGES 800000
#define D 128

// Scratch (static device allocations are allowed; cudaMalloc is not)
__device__ float g_agg[N_NODES * D];        // segment_sum result, 25.6 MB
__device__ float g_Bt[2 * D * D];           // combined transposed weights [256][128]
__device__ int   g_is64;                    // edge_index dtype flag

// ---------------------------------------------------------------------------
// Detect whether edge_index is int64 or int32.
// If int64 with values < 2^31, every odd 32-bit word of the first 32 entries
// is zero. For int32 random indices in [0, 50000) that is astronomically
// unlikely.
__global__ void detect_dtype_kernel(const int* __restrict__ ei32) {
    if (threadIdx.x == 0 && blockIdx.x == 0) {
        int looks64 = 1;
        #pragma unroll
        for (int i = 1; i < 64; i += 2) {
            if (ei32[i] != 0) looks64 = 0;
        }
        g_is64 = looks64;
    }
}

// ---------------------------------------------------------------------------
// Zero the aggregation buffer (float4 grid-stride)
__global__ void zero_agg_kernel() {
    int i = blockIdx.x * blockDim.x + threadIdx.x;
    const int n4 = N_NODES * D / 4;
    float4* p = reinterpret_cast<float4*>(g_agg);
    if (i < n4) p[i] = make_float4(0.f, 0.f, 0.f, 0.f);
}

// ---------------------------------------------------------------------------
// Build Bt[k][n]: k<128 -> W_rel[n][k], k>=128 -> W_root[n][k-128]
__global__ void build_Bt_kernel(const float* __restrict__ W_rel,
                                const float* __restrict__ W_root) {
    int idx = blockIdx.x * blockDim.x + threadIdx.x;
    if (idx < 2 * D * D) {
        int k = idx / D;
        int n = idx % D;
        g_Bt[idx] = (k < D) ? W_rel[n * D + k] : W_root[n * D + (k - D)];
    }
}

// ---------------------------------------------------------------------------
// Scatter-add: one warp per edge. Lane l handles float4 #l of the 128-float row.
__global__ __launch_bounds__(256) void scatter_kernel(
    const float* __restrict__ x,
    const void*  __restrict__ ei_raw) {
    int gtid = blockIdx.x * blockDim.x + threadIdx.x;
    int e    = gtid >> 5;
    int lane = threadIdx.x & 31;
    if (e >= N_EDGES) return;

    long long s, d;
    if (g_is64) {
        const long long* ei = (const long long*)ei_raw;
        s = ei[e];
        d = ei[N_EDGES + e];
    } else {
        const int* ei = (const int*)ei_raw;
        s = ei[e];
        d = ei[N_EDGES + e];
    }

    float4 v = reinterpret_cast<const float4*>(x + s * D)[lane];
#if __CUDA_ARCH__ >= 900
    atomicAdd(reinterpret_cast<float4*>(g_agg + d * D) + lane, v);
#else
    float* dst = g_agg + d * D + lane * 4;
    atomicAdd(dst + 0, v.x);
    atomicAdd(dst + 1, v.y);
    atomicAdd(dst + 2, v.z);
    atomicAdd(dst + 3, v.w);
#endif
}

// ---------------------------------------------------------------------------
// Fused GEMM + bias + ReLU:
//   C[M=50000, N=128] = A[M, 256] * Bt[256, 128],  A = [agg | x]
// Block tile 128x128, BK=16, 256 threads, 8x8 outputs per thread.
__global__ __launch_bounds__(256) void gemm_relu_kernel(
    const float* __restrict__ x,
    const float* __restrict__ bias,
    float*       __restrict__ out) {
    __shared__ float As[16][128];   // [k][m]
    __shared__ float Bs[16][128];   // [k][n]

    const int m0  = blockIdx.x * 128;
    const int tid = threadIdx.x;
    const int tx  = tid & 15;       // col group
    const int ty  = tid >> 4;       // row group

    float acc[8][8];
    #pragma unroll
    for (int i = 0; i < 8; i++)
        #pragma unroll
        for (int j = 0; j < 8; j++) acc[i][j] = 0.f;

    for (int kt = 0; kt < 256; kt += 16) {
        // A source: first 128 k's come from g_agg, last 128 from x
        const float* Asrc = (kt < 128) ? (g_agg + kt) : (x + (kt - 128));

        #pragma unroll
        for (int l = 0; l < 2; l++) {
            int linear = tid * 2 + l;          // 0..511, each names one float4
            // --- A tile: 128 rows x 16 k, float4 over k ---
            int row = linear >> 2;             // 0..127
            int kk  = (linear & 3) * 4;        // 0,4,8,12
            int m   = m0 + row;
            int mc  = (m < N_NODES) ? m : (N_NODES - 1);   // clamp OOB rows
            float4 va = *reinterpret_cast<const float4*>(Asrc + (size_t)mc * D + kk);
            As[kk + 0][row] = va.x;
            As[kk + 1][row] = va.y;
            As[kk + 2][row] = va.z;
            As[kk + 3][row] = va.w;
            // --- B tile: 16 k x 128 n, contiguous float4 ---
            int bk = linear >> 5;              // 0..15
            int bn = (linear & 31) * 4;        // 0..124
            float4 vb = *reinterpret_cast<const float4*>(
                g_Bt + (size_t)(kt + bk) * D + bn);
            *reinterpret_cast<float4*>(&Bs[bk][bn]) = vb;
        }
        __syncthreads();

        #pragma unroll
        for (int kk = 0; kk < 16; kk++) {
            float a[8], b[8];
            #pragma unroll
            for (int i = 0; i < 8; i++) a[i] = As[kk][ty * 8 + i];
            #pragma unroll
            for (int j = 0; j < 8; j++) b[j] = Bs[kk][tx * 8 + j];
            #pragma unroll
            for (int i = 0; i < 8; i++)
                #pragma unroll
                for (int j = 0; j < 8; j++)
                    acc[i][j] += a[i] * b[j];
        }
        __syncthreads();
    }

    // Epilogue: + bias, ReLU, store
    float bb[8];
    #pragma unroll
    for (int j = 0; j < 8; j++) bb[j] = bias[tx * 8 + j];

    #pragma unroll
    for (int i = 0; i < 8; i++) {
        int m = m0 + ty * 8 + i;
        if (m >= N_NODES) continue;
        float* orow = out + (size_t)m * D + tx * 8;
        #pragma unroll
        for (int j = 0; j < 8; j++) {
            float v = acc[i][j] + bb[j];
            orow[j] = v > 0.f ? v : 0.f;
        }
    }
}

// ---------------------------------------------------------------------------
extern "C" void kernel_launch(void* const* d_in, const int* in_sizes, int n_in,
                              void* d_out, int out_size) {
    const float* x      = (const float*)d_in[0];
    const void*  ei     = d_in[1];
    const float* W_rel  = (const float*)d_in[2];
    const float* b_rel  = (const float*)d_in[3];
    const float* W_root = (const float*)d_in[4];
    float*       out    = (float*)d_out;

    // Prep: dtype detect, zero agg, build transposed combined weights
    detect_dtype_kernel<<<1, 32>>>((const int*)ei);
    {
        int n4 = N_NODES * D / 4;
        zero_agg_kernel<<<(n4 + 255) / 256, 256>>>();
    }
    build_Bt_kernel<<<(2 * D * D + 255) / 256, 256>>>(W_rel, W_root);

    // Scatter-add: one warp per edge
    {
        long long total_threads = (long long)N_EDGES * 32;
        int blocks = (int)((total_threads + 255) / 256);
        scatter_kernel<<<blocks, 256>>>(x, ei);
    }

    // Fused dual-GEMM + bias + ReLU
    {
        int blocks = (N_NODES + 127) / 128;
        gemm_relu_kernel<<<blocks, 256>>>(x, b_rel, out);
    }
}

// round 4
// speedup vs baseline: 1.2886x; 1.2886x over previous
#include <cuda_runtime.h>
#include <cuda_bf16.h>
#include <cstdint>

#define N_NODES 50000
#define N_EDGES 800000
#define D 128

// ---------------------------------------------------------------------------
// Scratch
__device__ float g_agg[N_NODES * D];            // segment_sum result, 25.6 MB
__device__ int   g_is64;                        // edge_index dtype flag
// bf16 weight images, plain row-major [n][k]:
// [0]=W_rel hi, [1]=W_rel lo, [2]=W_root hi, [3]=W_root lo
__device__ __nv_bfloat16 g_B[4][D * D];

// ---------------------------------------------------------------------------
__device__ __forceinline__ uint32_t smem_u32(const void* p) {
    uint32_t a;
    asm("{ .reg .u64 t; cvta.to.shared.u64 t, %1; cvt.u32.u64 %0, t; }" : "=r"(a) : "l"(p));
    return a;
}
__device__ __forceinline__ void ldsm_x4(uint32_t* r, uint32_t addr) {
    asm volatile("ldmatrix.sync.aligned.m8n8.x4.shared.b16 {%0,%1,%2,%3}, [%4];"
        : "=r"(r[0]), "=r"(r[1]), "=r"(r[2]), "=r"(r[3]) : "r"(addr));
}
__device__ __forceinline__ void mma16816(float* c, const uint32_t* a,
                                         uint32_t b0, uint32_t b1) {
    asm volatile("mma.sync.aligned.m16n8k16.row.col.f32.bf16.bf16.f32 "
        "{%0,%1,%2,%3}, {%4,%5,%6,%7}, {%8,%9}, {%0,%1,%2,%3};"
        : "+f"(c[0]), "+f"(c[1]), "+f"(c[2]), "+f"(c[3])
        : "r"(a[0]), "r"(a[1]), "r"(a[2]), "r"(a[3]), "r"(b0), "r"(b1));
}

// ---------------------------------------------------------------------------
// dtype detection (int64 vs int32 edge_index)
__global__ void detect_dtype_kernel(const int* __restrict__ ei32) {
    if (threadIdx.x == 0 && blockIdx.x == 0) {
        int looks64 = 1;
        #pragma unroll
        for (int i = 1; i < 64; i += 2)
            if (ei32[i] != 0) looks64 = 0;
        g_is64 = looks64;
    }
}

// Zero agg buffer
__global__ void zero_agg_kernel() {
    int i = blockIdx.x * blockDim.x + threadIdx.x;
    const int n4 = N_NODES * D / 4;
    float4* p = reinterpret_cast<float4*>(g_agg);
    if (i < n4) p[i] = make_float4(0.f, 0.f, 0.f, 0.f);
}

// Build bf16 hi/lo weight images (row-major [n][k])
__global__ void build_B_kernel(const float* __restrict__ W_rel,
                               const float* __restrict__ W_root) {
    int idx = blockIdx.x * blockDim.x + threadIdx.x;   // 2*128*128
    if (idx >= 2 * D * D) return;
    int h = idx >> 14;                 // 0: W_rel, 1: W_root
    int r = idx & 16383;               // n*128 + k
    float v = h ? W_root[r] : W_rel[r];
    __nv_bfloat16 hi = __float2bfloat16(v);
    __nv_bfloat16 lo = __float2bfloat16(v - __bfloat162float(hi));
    g_B[2 * h + 0][r] = hi;
    g_B[2 * h + 1][r] = lo;
}

// ---------------------------------------------------------------------------
// Scatter-add: one warp per edge (93us, L2-atomic bound)
__global__ __launch_bounds__(256) void scatter_kernel(
    const float* __restrict__ x,
    const void*  __restrict__ ei_raw) {
    int gtid = blockIdx.x * blockDim.x + threadIdx.x;
    int e    = gtid >> 5;
    int lane = threadIdx.x & 31;
    if (e >= N_EDGES) return;

    long long s, d;
    if (g_is64) {
        const long long* ei = (const long long*)ei_raw;
        s = ei[e];
        d = ei[N_EDGES + e];
    } else {
        const int* ei = (const int*)ei_raw;
        s = ei[e];
        d = ei[N_EDGES + e];
    }

    float4 v = reinterpret_cast<const float4*>(x + s * D)[lane];
    atomicAdd(reinterpret_cast<float4*>(g_agg + d * D) + lane, v);
}

// ---------------------------------------------------------------------------
// HMMA bf16x3 dual-GEMM + bias + ReLU
//   C[128-tile, 128] = agg @ W_rel^T + x @ W_root^T   (fp32 accum)
// smem: A hi/lo [128][136] bf16 (re-staged per pass), B all 4 images [128][136]
#define LDA   136                         // 128 + 8 pad (conflict-free ldmatrix)
#define TILE_B (128 * LDA * 2)            // 34816 bytes
#define AS_HI  0
#define AS_LO  TILE_B
#define BS(b)  (2 * TILE_B + (b) * TILE_B)
#define SM_TOTAL (6 * TILE_B)             // 208896 bytes

__global__ __launch_bounds__(256, 1) void gemm_hmma_kernel(
    const float* __restrict__ x,
    const float* __restrict__ bias,
    float*       __restrict__ out) {
    extern __shared__ char smem[];
    const uint32_t sb  = smem_u32(smem);
    const int tid  = threadIdx.x;
    const int wid  = tid >> 5;
    const int lane = tid & 31;
    const int wm   = wid & 3;             // warp row: 32 rows each
    const int wn   = wid >> 2;            // warp col: 64 cols each
    const int m0   = blockIdx.x * 128;

    // ---- Stage all 4 B images: gmem bf16 -> padded smem -------------------
    #pragma unroll
    for (int b = 0; b < 4; b++) {
        const uint4* src = reinterpret_cast<const uint4*>(&g_B[b][0]);
        #pragma unroll
        for (int i = 0; i < 8; i++) {
            int c  = tid + i * 256;       // 2048 16B-chunks
            int n  = c >> 4;
            int k8 = (c & 15) * 8;
            uint4 v = src[c];
            *reinterpret_cast<uint4*>(smem + BS(b) + (n * LDA + k8) * 2) = v;
        }
    }

    float acc[2][8][4];
    #pragma unroll
    for (int i = 0; i < 2; i++)
        #pragma unroll
        for (int j = 0; j < 8; j++)
            #pragma unroll
            for (int q = 0; q < 4; q++) acc[i][j][q] = 0.f;

    // ---- Two K-passes: pass 0 = agg @ W_rel, pass 1 = x @ W_root ----------
    #pragma unroll
    for (int pass = 0; pass < 2; pass++) {
        // Stage + split A tile: 128 rows x 128 fp32 -> bf16 hi/lo, padded.
        {
            const float* src = pass ? x : g_agg;
            int r  = tid >> 1;
            int c0 = (tid & 1) * 64;
            int m  = m0 + r;
            if (m >= N_NODES) m = N_NODES - 1;   // clamp; stores guarded later
            const float4* row4 = reinterpret_cast<const float4*>(src + (size_t)m * D + c0);
            #pragma unroll
            for (int j = 0; j < 8; j++) {
                float4 f0 = row4[j * 2 + 0];
                float4 f1 = row4[j * 2 + 1];
                float f[8] = {f0.x, f0.y, f0.z, f0.w, f1.x, f1.y, f1.z, f1.w};
                uint32_t hi[4], lo[4];
                #pragma unroll
                for (int q = 0; q < 4; q++) {
                    float a = f[2 * q], b = f[2 * q + 1];
                    __nv_bfloat162 h2 = __floats2bfloat162_rn(a, b);
                    float la = a - __bfloat162float(__low2bfloat16(h2));
                    float lb = b - __bfloat162float(__high2bfloat16(h2));
                    __nv_bfloat162 l2 = __floats2bfloat162_rn(la, lb);
                    hi[q] = *reinterpret_cast<uint32_t*>(&h2);
                    lo[q] = *reinterpret_cast<uint32_t*>(&l2);
                }
                uint32_t off = (uint32_t)(r * LDA + c0 + j * 8) * 2;
                *reinterpret_cast<uint4*>(smem + AS_HI + off) = make_uint4(hi[0], hi[1], hi[2], hi[3]);
                *reinterpret_cast<uint4*>(smem + AS_LO + off) = make_uint4(lo[0], lo[1], lo[2], lo[3]);
            }
        }
        __syncthreads();

        const uint32_t bs_hi = sb + BS(2 * pass);
        const uint32_t bs_lo = sb + BS(2 * pass + 1);

        // ldmatrix lane-address components
        const int arow = (lane & 15);         // row within 16-row tile
        const int acol = (lane >> 4) * 8;     // 0 or 8 (k within 16-k step)

        #pragma unroll
        for (int kk = 0; kk < 8; kk++) {
            const int kbase = kk * 16 + acol;
            // A fragments (hi & lo) for the warp's two 16-row tiles
            uint32_t ah[2][4], al[2][4];
            #pragma unroll
            for (int mt = 0; mt < 2; mt++) {
                uint32_t off = (uint32_t)((wm * 32 + mt * 16 + arow) * LDA + kbase) * 2;
                ldsm_x4(ah[mt], sb + AS_HI + off);
                ldsm_x4(al[mt], sb + AS_LO + off);
            }
            // B: 4 n16-groups per warp.
            // ldmatrix.x4 register order here: r0=(n0-7,k0-7), r1=(n8-15,k0-7),
            //                                  r2=(n0-7,k8-15), r3=(n8-15,k8-15)
            // => n-tile 0 operand = {r0, r2}, n-tile 1 operand = {r1, r3}.
            #pragma unroll
            for (int ng = 0; ng < 4; ng++) {
                uint32_t boff = (uint32_t)((wn * 64 + ng * 16 + arow) * LDA + kbase) * 2;
                uint32_t bh[4], bl[4];
                ldsm_x4(bh, bs_hi + boff);
                ldsm_x4(bl, bs_lo + boff);
                #pragma unroll
                for (int mt = 0; mt < 2; mt++) {
                    mma16816(acc[mt][2 * ng + 0], ah[mt], bh[0], bh[2]);
                    mma16816(acc[mt][2 * ng + 1], ah[mt], bh[1], bh[3]);
                    mma16816(acc[mt][2 * ng + 0], ah[mt], bl[0], bl[2]);
                    mma16816(acc[mt][2 * ng + 1], ah[mt], bl[1], bl[3]);
                    mma16816(acc[mt][2 * ng + 0], al[mt], bh[0], bh[2]);
                    mma16816(acc[mt][2 * ng + 1], al[mt], bh[1], bh[3]);
                }
            }
        }
        __syncthreads();   // before next pass overwrites As
    }

    // ---- Epilogue: + bias, ReLU, store ------------------------------------
    #pragma unroll
    for (int mt = 0; mt < 2; mt++) {
        int r0 = m0 + wm * 32 + mt * 16 + (lane >> 2);
        #pragma unroll
        for (int nt = 0; nt < 8; nt++) {
            int n = wn * 64 + nt * 8 + (lane & 3) * 2;
            float2 bb = __ldg(reinterpret_cast<const float2*>(bias + n));
            float* a4 = acc[mt][nt];
            if (r0 < N_NODES) {
                float2 v;
                v.x = a4[0] + bb.x; v.y = a4[1] + bb.y;
                v.x = v.x > 0.f ? v.x : 0.f;
                v.y = v.y > 0.f ? v.y : 0.f;
                *reinterpret_cast<float2*>(out + (size_t)r0 * D + n) = v;
            }
            if (r0 + 8 < N_NODES) {
                float2 v;
                v.x = a4[2] + bb.x; v.y = a4[3] + bb.y;
                v.x = v.x > 0.f ? v.x : 0.f;
                v.y = v.y > 0.f ? v.y : 0.f;
                *reinterpret_cast<float2*>(out + (size_t)(r0 + 8) * D + n) = v;
            }
        }
    }
}

// ---------------------------------------------------------------------------
extern "C" void kernel_launch(void* const* d_in, const int* in_sizes, int n_in,
                              void* d_out, int out_size) {
    const float* x      = (const float*)d_in[0];
    const void*  ei     = d_in[1];
    const float* W_rel  = (const float*)d_in[2];
    const float* b_rel  = (const float*)d_in[3];
    const float* W_root = (const float*)d_in[4];
    float*       out    = (float*)d_out;

    cudaFuncSetAttribute(gemm_hmma_kernel,
                         cudaFuncAttributeMaxDynamicSharedMemorySize, SM_TOTAL);

    detect_dtype_kernel<<<1, 32>>>((const int*)ei);
    {
        int n4 = N_NODES * D / 4;
        zero_agg_kernel<<<(n4 + 255) / 256, 256>>>();
    }
    build_B_kernel<<<(2 * D * D + 255) / 256, 256>>>(W_rel, W_root);

    {
        long long total_threads = (long long)N_EDGES * 32;
        int blocks = (int)((total_threads + 255) / 256);
        scatter_kernel<<<blocks, 256>>>(x, ei);
    }

    {
        int blocks = (N_NODES + 127) / 128;
        gemm_hmma_kernel<<<blocks, 256, SM_TOTAL>>>(x, b_rel, out);
    }
}

// round 7
// speedup vs baseline: 1.6509x; 1.2811x over previous
#include <cuda_runtime.h>
#include <cuda_bf16.h>
#include <cstdint>

#define N_NODES 50000
#define N_EDGES 800000
#define D 128
#define NSCAN_BLK 196                     // ceil(50000/256)

// ---------------------------------------------------------------------------
// Scratch
__device__ float g_agg[N_NODES * D];      // segment_sum result
__device__ int   g_is64;                  // edge_index dtype flag
__device__ __nv_bfloat16 g_B[4][D * D];   // W_rel hi/lo, W_root hi/lo
__device__ int g_hist[N_NODES];
__device__ int g_excl[N_NODES];
__device__ int g_bsum[NSCAN_BLK];
__device__ int g_bsum_scan[NSCAN_BLK];
__device__ int g_row_ptr[N_NODES + 1];
__device__ int g_cursor[N_NODES];
__device__ int g_src_sorted[N_EDGES];

// ---------------------------------------------------------------------------
__device__ __forceinline__ uint32_t smem_u32(const void* p) {
    uint32_t a;
    asm("{ .reg .u64 t; cvta.to.shared.u64 t, %1; cvt.u32.u64 %0, t; }" : "=r"(a) : "l"(p));
    return a;
}
__device__ __forceinline__ void ldsm_x4(uint32_t* r, uint32_t addr) {
    asm volatile("ldmatrix.sync.aligned.m8n8.x4.shared.b16 {%0,%1,%2,%3}, [%4];"
        : "=r"(r[0]), "=r"(r[1]), "=r"(r[2]), "=r"(r[3]) : "r"(addr));
}
__device__ __forceinline__ void mma16816(float* c, const uint32_t* a,
                                         uint32_t b0, uint32_t b1) {
    asm volatile("mma.sync.aligned.m16n8k16.row.col.f32.bf16.bf16.f32 "
        "{%0,%1,%2,%3}, {%4,%5,%6,%7}, {%8,%9}, {%0,%1,%2,%3};"
        : "+f"(c[0]), "+f"(c[1]), "+f"(c[2]), "+f"(c[3])
        : "r"(a[0]), "r"(a[1]), "r"(a[2]), "r"(a[3]), "r"(b0), "r"(b1));
}
__device__ __forceinline__ long long load_idx(const void* ei, int pos, int is64) {
    if (is64) return ((const long long*)ei)[pos];
    return (long long)((const int*)ei)[pos];
}

// ---------------------------------------------------------------------------
__global__ void detect_dtype_kernel(const int* __restrict__ ei32) {
    if (threadIdx.x == 0 && blockIdx.x == 0) {
        int looks64 = 1;
        #pragma unroll
        for (int i = 1; i < 64; i += 2)
            if (ei32[i] != 0) looks64 = 0;
        g_is64 = looks64;
    }
}

__global__ void zero_hist_kernel() {
    int i = blockIdx.x * blockDim.x + threadIdx.x;
    if (i < N_NODES) g_hist[i] = 0;
}

__global__ void build_B_kernel(const float* __restrict__ W_rel,
                               const float* __restrict__ W_root) {
    int idx = blockIdx.x * blockDim.x + threadIdx.x;
    if (idx >= 2 * D * D) return;
    int h = idx >> 14;
    int r = idx & 16383;
    float v = h ? W_root[r] : W_rel[r];
    __nv_bfloat16 hi = __float2bfloat16(v);
    __nv_bfloat16 lo = __float2bfloat16(v - __bfloat162float(hi));
    g_B[2 * h + 0][r] = hi;
    g_B[2 * h + 1][r] = lo;
}

// ---- counting sort by dst --------------------------------------------------
__global__ __launch_bounds__(256) void hist_kernel(const void* __restrict__ ei) {
    int e = blockIdx.x * blockDim.x + threadIdx.x;
    if (e >= N_EDGES) return;
    int d = (int)load_idx(ei, N_EDGES + e, g_is64);
    atomicAdd(&g_hist[d], 1);
}

__global__ __launch_bounds__(256) void scan1_kernel() {
    __shared__ int sh[256];
    int i = blockIdx.x * 256 + threadIdx.x;
    int v = (i < N_NODES) ? g_hist[i] : 0;
    sh[threadIdx.x] = v;
    __syncthreads();
    #pragma unroll
    for (int off = 1; off < 256; off <<= 1) {
        int t = (threadIdx.x >= off) ? sh[threadIdx.x - off] : 0;
        __syncthreads();
        sh[threadIdx.x] += t;
        __syncthreads();
    }
    int incl = sh[threadIdx.x];
    if (i < N_NODES) g_excl[i] = incl - v;
    if (threadIdx.x == 255) g_bsum[blockIdx.x] = incl;
}

__global__ __launch_bounds__(256) void scan2_kernel() {
    __shared__ int sh[256];
    int v = (threadIdx.x < NSCAN_BLK) ? g_bsum[threadIdx.x] : 0;
    sh[threadIdx.x] = v;
    __syncthreads();
    #pragma unroll
    for (int off = 1; off < 256; off <<= 1) {
        int t = (threadIdx.x >= off) ? sh[threadIdx.x - off] : 0;
        __syncthreads();
        sh[threadIdx.x] += t;
        __syncthreads();
    }
    if (threadIdx.x < NSCAN_BLK) g_bsum_scan[threadIdx.x] = sh[threadIdx.x] - v;
}

__global__ __launch_bounds__(256) void scan3_kernel() {
    int i = blockIdx.x * 256 + threadIdx.x;
    if (i < N_NODES) {
        int rp = g_excl[i] + g_bsum_scan[i >> 8];
        g_row_ptr[i] = rp;
        g_cursor[i]  = rp;
        if (i == 0) g_row_ptr[N_NODES] = N_EDGES;
    }
}

__global__ __launch_bounds__(256) void permute_kernel(const void* __restrict__ ei) {
    int e = blockIdx.x * blockDim.x + threadIdx.x;
    if (e >= N_EDGES) return;
    int is64 = g_is64;
    int s = (int)load_idx(ei, e, is64);
    int d = (int)load_idx(ei, N_EDGES + e, is64);
    int pos = atomicAdd(&g_cursor[d], 1);
    g_src_sorted[pos] = s;
}

// ---- atomic-free aggregation: one warp per node ---------------------------
__global__ __launch_bounds__(256) void aggregate_kernel(const float* __restrict__ x) {
    int w    = (blockIdx.x * blockDim.x + threadIdx.x) >> 5;
    int lane = threadIdx.x & 31;
    if (w >= N_NODES) return;

    int beg = g_row_ptr[w];
    int end = g_row_ptr[w + 1];

    float4 acc = make_float4(0.f, 0.f, 0.f, 0.f);
    const float4* x4 = reinterpret_cast<const float4*>(x);

    for (int j0 = beg; j0 < end; j0 += 32) {
        int cnt = min(32, end - j0);
        int myidx = (j0 + lane < end) ? g_src_sorted[j0 + lane] : 0;
        for (int t = 0; t < cnt; t++) {
            int s = __shfl_sync(0xffffffffu, myidx, t);
            float4 v = x4[(size_t)s * 32 + lane];
            acc.x += v.x; acc.y += v.y; acc.z += v.z; acc.w += v.w;
        }
    }
    reinterpret_cast<float4*>(g_agg)[(size_t)w * 32 + lane] = acc;
}

// ---------------------------------------------------------------------------
// HMMA bf16x3 dual-GEMM + bias + ReLU (unchanged from R4)
#define LDA   136
#define TILE_B (128 * LDA * 2)
#define AS_HI  0
#define AS_LO  TILE_B
#define BS(b)  (2 * TILE_B + (b) * TILE_B)
#define SM_TOTAL (6 * TILE_B)

__global__ __launch_bounds__(256, 1) void gemm_hmma_kernel(
    const float* __restrict__ x,
    const float* __restrict__ bias,
    float*       __restrict__ out) {
    extern __shared__ char smem[];
    const uint32_t sb  = smem_u32(smem);
    const int tid  = threadIdx.x;
    const int wid  = tid >> 5;
    const int lane = tid & 31;
    const int wm   = wid & 3;
    const int wn   = wid >> 2;
    const int m0   = blockIdx.x * 128;

    #pragma unroll
    for (int b = 0; b < 4; b++) {
        const uint4* src = reinterpret_cast<const uint4*>(&g_B[b][0]);
        #pragma unroll
        for (int i = 0; i < 8; i++) {
            int c  = tid + i * 256;
            int n  = c >> 4;
            int k8 = (c & 15) * 8;
            uint4 v = src[c];
            *reinterpret_cast<uint4*>(smem + BS(b) + (n * LDA + k8) * 2) = v;
        }
    }

    float acc[2][8][4];
    #pragma unroll
    for (int i = 0; i < 2; i++)
        #pragma unroll
        for (int j = 0; j < 8; j++)
            #pragma unroll
            for (int q = 0; q < 4; q++) acc[i][j][q] = 0.f;

    #pragma unroll
    for (int pass = 0; pass < 2; pass++) {
        {
            const float* src = pass ? x : g_agg;
            int r  = tid >> 1;
            int c0 = (tid & 1) * 64;
            int m  = m0 + r;
            if (m >= N_NODES) m = N_NODES - 1;
            const float4* row4 = reinterpret_cast<const float4*>(src + (size_t)m * D + c0);
            #pragma unroll
            for (int j = 0; j < 8; j++) {
                float4 f0 = row4[j * 2 + 0];
                float4 f1 = row4[j * 2 + 1];
                float f[8] = {f0.x, f0.y, f0.z, f0.w, f1.x, f1.y, f1.z, f1.w};
                uint32_t hi[4], lo[4];
                #pragma unroll
                for (int q = 0; q < 4; q++) {
                    float a = f[2 * q], b = f[2 * q + 1];
                    __nv_bfloat162 h2 = __floats2bfloat162_rn(a, b);
                    float la = a - __bfloat162float(__low2bfloat16(h2));
                    float lb = b - __bfloat162float(__high2bfloat16(h2));
                    __nv_bfloat162 l2 = __floats2bfloat162_rn(la, lb);
                    hi[q] = *reinterpret_cast<uint32_t*>(&h2);
                    lo[q] = *reinterpret_cast<uint32_t*>(&l2);
                }
                uint32_t off = (uint32_t)(r * LDA + c0 + j * 8) * 2;
                *reinterpret_cast<uint4*>(smem + AS_HI + off) = make_uint4(hi[0], hi[1], hi[2], hi[3]);
                *reinterpret_cast<uint4*>(smem + AS_LO + off) = make_uint4(lo[0], lo[1], lo[2], lo[3]);
            }
        }
        __syncthreads();

        const uint32_t bs_hi = sb + BS(2 * pass);
        const uint32_t bs_lo = sb + BS(2 * pass + 1);
        const int arow = (lane & 15);
        const int acol = (lane >> 4) * 8;

        #pragma unroll
        for (int kk = 0; kk < 8; kk++) {
            const int kbase = kk * 16 + acol;
            uint32_t ah[2][4], al[2][4];
            #pragma unroll
            for (int mt = 0; mt < 2; mt++) {
                uint32_t off = (uint32_t)((wm * 32 + mt * 16 + arow) * LDA + kbase) * 2;
                ldsm_x4(ah[mt], sb + AS_HI + off);
                ldsm_x4(al[mt], sb + AS_LO + off);
            }
            #pragma unroll
            for (int ng = 0; ng < 4; ng++) {
                uint32_t boff = (uint32_t)((wn * 64 + ng * 16 + arow) * LDA + kbase) * 2;
                uint32_t bh[4], bl[4];
                ldsm_x4(bh, bs_hi + boff);
                ldsm_x4(bl, bs_lo + boff);
                #pragma unroll
                for (int mt = 0; mt < 2; mt++) {
                    mma16816(acc[mt][2 * ng + 0], ah[mt], bh[0], bh[2]);
                    mma16816(acc[mt][2 * ng + 1], ah[mt], bh[1], bh[3]);
                    mma16816(acc[mt][2 * ng + 0], ah[mt], bl[0], bl[2]);
                    mma16816(acc[mt][2 * ng + 1], ah[mt], bl[1], bl[3]);
                    mma16816(acc[mt][2 * ng + 0], al[mt], bh[0], bh[2]);
                    mma16816(acc[mt][2 * ng + 1], al[mt], bh[1], bh[3]);
                }
            }
        }
        __syncthreads();
    }

    #pragma unroll
    for (int mt = 0; mt < 2; mt++) {
        int r0 = m0 + wm * 32 + mt * 16 + (lane >> 2);
        #pragma unroll
        for (int nt = 0; nt < 8; nt++) {
            int n = wn * 64 + nt * 8 + (lane & 3) * 2;
            float2 bb = __ldg(reinterpret_cast<const float2*>(bias + n));
            float* a4 = acc[mt][nt];
            if (r0 < N_NODES) {
                float2 v;
                v.x = a4[0] + bb.x; v.y = a4[1] + bb.y;
                v.x = v.x > 0.f ? v.x : 0.f;
                v.y = v.y > 0.f ? v.y : 0.f;
                *reinterpret_cast<float2*>(out + (size_t)r0 * D + n) = v;
            }
            if (r0 + 8 < N_NODES) {
                float2 v;
                v.x = a4[2] + bb.x; v.y = a4[3] + bb.y;
                v.x = v.x > 0.f ? v.x : 0.f;
                v.y = v.y > 0.f ? v.y : 0.f;
                *reinterpret_cast<float2*>(out + (size_t)(r0 + 8) * D + n) = v;
            }
        }
    }
}

// ---------------------------------------------------------------------------
extern "C" void kernel_launch(void* const* d_in, const int* in_sizes, int n_in,
                              void* d_out, int out_size) {
    const float* x      = (const float*)d_in[0];
    const void*  ei     = d_in[1];
    const float* W_rel  = (const float*)d_in[2];
    const float* b_rel  = (const float*)d_in[3];
    const float* W_root = (const float*)d_in[4];
    float*       out    = (float*)d_out;

    cudaFuncSetAttribute(gemm_hmma_kernel,
                         cudaFuncAttributeMaxDynamicSharedMemorySize, SM_TOTAL);

    detect_dtype_kernel<<<1, 32>>>((const int*)ei);
    zero_hist_kernel<<<NSCAN_BLK, 256>>>();
    build_B_kernel<<<(2 * D * D + 255) / 256, 256>>>(W_rel, W_root);

    const int EB = (N_EDGES + 255) / 256;
    hist_kernel<<<EB, 256>>>(ei);
    scan1_kernel<<<NSCAN_BLK, 256>>>();
    scan2_kernel<<<1, 256>>>();
    scan3_kernel<<<NSCAN_BLK, 256>>>();
    permute_kernel<<<EB, 256>>>(ei);

    {
        int blocks = (N_NODES * 32 + 255) / 256;
        aggregate_kernel<<<blocks, 256>>>(x);
    }
    {
        int blocks = (N_NODES + 127) / 128;
        gemm_hmma_kernel<<<blocks, 256, SM_TOTAL>>>(x, b_rel, out);
    }
}